// round 14
// baseline (speedup 1.0000x reference)
#include <cuda_runtime.h>
#include <cuda_fp16.h>
#include <cstdint>

#define DT_STEP 0.01f
#define GRID_SMS 152
#define NUM_S32 4096                    // 131072 rows / 32
#define NPAIRS 8
#define ROW_B 272                       // 128 f16 (256B) + 16B pad
#define T32 (32 * ROW_B)                // 32-row strip = 8704 B

#define S_W1  0
#define S_W2  (S_W1 + 128 * ROW_B)
#define S_B1  (S_W2 + 128 * ROW_B)
#define S_B2  (S_B1 + 512)
#define S_POP (S_B2 + 512)
#define S_Q   (S_POP + 512)             // 8 pairs x 2 strips (roles swap)
#define S_TOT (S_Q + NPAIRS * 2 * T32)  // 71168 + 139264 = 210432 B

__device__ unsigned int g_ctr;
__global__ void reset_ctr() { g_ctr = 0u; }

// ---------------- helpers ----------------
static __device__ __forceinline__ uint32_t smem_u32(const void* p) {
    uint32_t a;
    asm("{ .reg .u64 t; cvta.to.shared.u64 t, %1; cvt.u32.u64 %0, t; }" : "=r"(a) : "l"(p));
    return a;
}

static __device__ __forceinline__ uint32_t packhf(float a, float b) {
    __half2 t = __floats2half2_rn(a, b);
    return *reinterpret_cast<uint32_t*>(&t);
}

static __device__ __forceinline__ float2 unpackhf(uint32_t v) {
    return __half22float2(*reinterpret_cast<__half2*>(&v));
}

static __device__ __forceinline__ float tanh_fast(float v) {
    float r;
    asm("tanh.approx.f32 %0, %1;" : "=f"(r) : "f"(v));
    return r;
}

static __device__ __forceinline__ void ldsm_x4(uint32_t* r, uint32_t addr) {
    asm volatile("ldmatrix.sync.aligned.m8n8.x4.shared.b16 {%0,%1,%2,%3}, [%4];"
                 : "=r"(r[0]), "=r"(r[1]), "=r"(r[2]), "=r"(r[3]) : "r"(addr));
}

static __device__ __forceinline__ void ldsm_x4_t(uint32_t* r, uint32_t addr) {
    asm volatile("ldmatrix.sync.aligned.m8n8.x4.trans.shared.b16 {%0,%1,%2,%3}, [%4];"
                 : "=r"(r[0]), "=r"(r[1]), "=r"(r[2]), "=r"(r[3]) : "r"(addr));
}

static __device__ __forceinline__ void mma16816h(uint32_t* d, const uint32_t* a,
                                                 const uint32_t* b) {
    asm volatile("mma.sync.aligned.m16n8k16.row.col.f16.f16.f16.f16 "
                 "{%0,%1}, {%2,%3,%4,%5}, {%6,%7}, {%0,%1};"
                 : "+r"(d[0]), "+r"(d[1])
                 : "r"(a[0]), "r"(a[1]), "r"(a[2]), "r"(a[3]), "r"(b[0]), "r"(b[1]));
}

// 32x64 warp GEMM: A = 32 rows (abase already includes per-lane amRow),
// B = N-half of W. B double-buffered; each B load serves both 16-row halves.
static __device__ __forceinline__ void gemm32x64_pipe(uint32_t abase, uint32_t wl,
                                                      uint32_t acc[8][2][2]) {
    uint32_t bb[2][4];
    ldsm_x4_t(bb[0], wl);               // (q0, nt0)
    int cur = 0;
    #pragma unroll
    for (int q = 0; q < 4; q++) {       // k32 chunks
        uint32_t afr[2][2][4];          // [kt][mt]
        #pragma unroll
        for (int kt = 0; kt < 2; kt++)
            #pragma unroll
            for (int mt = 0; mt < 2; mt++)
                ldsm_x4(afr[kt][mt], abase + (uint32_t)(mt * 16) * ROW_B
                                     + (uint32_t)(q * 64 + kt * 32));
        #pragma unroll
        for (int nt = 0; nt < 8; nt++) {
            const int idx = q * 8 + nt;
            if (idx < 31) {
                const int nq = (idx + 1) >> 3, nn = (idx + 1) & 7;
                ldsm_x4_t(bb[cur ^ 1], wl + (uint32_t)nq * (32 * ROW_B)
                                          + (uint32_t)nn * 16);
            }
            #pragma unroll
            for (int mt = 0; mt < 2; mt++)
                #pragma unroll
                for (int kt = 0; kt < 2; kt++)
                    mma16816h(acc[nt][mt], afr[kt][mt], &bb[cur][kt * 2]);
            cur ^= 1;
        }
    }
}

// ---------------- kernel ----------------
__global__ void __launch_bounds__(512, 1)
koopman_m32f(const float* __restrict__ x, const float* __restrict__ W1,
             const float* __restrict__ b1, const float* __restrict__ W2,
             const float* __restrict__ b2, float* __restrict__ out)
{
    extern __shared__ char smem[];
    const uint32_t sb = smem_u32(smem);
    const int tid  = threadIdx.x;
    const int lane = tid & 31;
    const int w    = tid >> 5;          // 0..15
    const int pair = w >> 1;            // 0..7
    const int wp   = w & 1;             // N-half owner
    const int g    = lane >> 2;
    const int t2   = (lane & 3) * 2;
    const int barid = pair + 1;

    // ---- one-time: stage W1, W2 (f16, padded rows) + biases ----
    #pragma unroll
    for (int j = 0; j < 8; j++) {
        int idx = j * 512 + tid;
        int r = idx >> 5, c4 = idx & 31;
        float4 wv = *(const float4*)(W1 + (size_t)r * 128 + c4 * 4);
        *(uint2*)(smem + S_W1 + r * ROW_B + c4 * 8) =
            make_uint2(packhf(wv.x, wv.y), packhf(wv.z, wv.w));
        float4 wv2 = *(const float4*)(W2 + (size_t)r * 128 + c4 * 4);
        *(uint2*)(smem + S_W2 + r * ROW_B + c4 * 8) =
            make_uint2(packhf(wv2.x, wv2.y), packhf(wv2.z, wv2.w));
    }
    if (tid < 128) {
        ((float*)(smem + S_B1))[tid] = b1[tid];
        ((float*)(smem + S_B2))[tid] = b2[tid];
    }
    __syncthreads();                    // only CTA-wide sync

    const uint32_t wl1 = sb + S_W1 + (uint32_t)lane * ROW_B + (uint32_t)wp * 128;
    const uint32_t wl2 = sb + S_W2 + (uint32_t)lane * ROW_B + (uint32_t)wp * 128;
    const int cbase = wp * 64;
    const float* fb1 = (const float*)(smem + S_B1) + cbase + t2;
    const float4 bq = *(const float4*)((const float*)(smem + S_B2) + lane * 4);
    volatile int* pop = (volatile int*)(smem + S_POP) + pair;

    const uint32_t amRow = (uint32_t)((lane & 7) + ((lane >> 3) & 1) * 8) * ROW_B
                         + (uint32_t)(lane >> 4) * 16;
    const int srow = wp * 16;           // this warp stages/epilogues 16 rows

    uint32_t bx = (uint32_t)(S_Q + pair * 2 * T32);   // x strip (role swaps)
    uint32_t bh = bx + T32;                            // H strip (role swaps)

    // ---- pop first unit, stage its x into bx ----
    if (wp == 0 && lane == 0) *pop = (int)atomicAdd(&g_ctr, 1u);
    asm volatile("bar.sync %0, 64;" :: "r"(barid) : "memory");
    int s = *pop;
    if (s < NUM_S32) {
        const float* xr = x + ((size_t)s * 32 + srow) * 128 + lane * 4;
        #pragma unroll
        for (int i = 0; i < 16; i++) {
            float4 v = *(const float4*)(xr + (size_t)i * 128);
            *(uint2*)(smem + bx + (srow + i) * ROW_B + lane * 8) =
                make_uint2(packhf(v.x, v.y), packhf(v.z, v.w));
        }
    }
    asm volatile("bar.sync %0, 64;" :: "r"(barid) : "memory");

    while (s < NUM_S32) {
        const size_t rbase = (size_t)s * 32;

        // ---- GEMM1: acc = X(32 rows) @ W1(:, half) ----
        uint32_t acc[8][2][2];
        #pragma unroll
        for (int nt = 0; nt < 8; nt++)
            #pragma unroll
            for (int mt = 0; mt < 2; mt++)
                { acc[nt][mt][0] = 0u; acc[nt][mt][1] = 0u; }
        gemm32x64_pipe(sb + bx + amRow, wl1, acc);

        // ---- epilogue 1: H half = tanh(acc + b1) -> bh; pop next id ----
        #pragma unroll
        for (int nt = 0; nt < 8; nt++) {
            float2 bv = *(const float2*)(fb1 + nt * 8);
            int c = cbase + nt * 8 + t2;
            #pragma unroll
            for (int mt = 0; mt < 2; mt++) {
                float2 p = unpackhf(acc[nt][mt][0]);
                float2 q = unpackhf(acc[nt][mt][1]);
                *(uint32_t*)(smem + bh + (mt * 16 + g) * ROW_B + c * 2) =
                    packhf(tanh_fast(p.x + bv.x), tanh_fast(p.y + bv.y));
                *(uint32_t*)(smem + bh + (mt * 16 + g + 8) * ROW_B + c * 2) =
                    packhf(tanh_fast(q.x + bv.x), tanh_fast(q.y + bv.y));
            }
        }
        if (wp == 0 && lane == 0) *pop = (int)atomicAdd(&g_ctr, 1u);
        asm volatile("bar.sync %0, 64;" :: "r"(barid) : "memory");   // H + pop ready

        // ---- GEMM2: acc = H(32 rows) @ W2(:, half) ----
        #pragma unroll
        for (int nt = 0; nt < 8; nt++)
            #pragma unroll
            for (int mt = 0; mt < 2; mt++)
                { acc[nt][mt][0] = 0u; acc[nt][mt][1] = 0u; }
        gemm32x64_pipe(sb + bh + amRow, wl2, acc);

        // ---- exchange: raw f16 (mu,omega) pairs -> bx (x dead after GEMM1) ----
        #pragma unroll
        for (int nt = 0; nt < 8; nt++) {
            uint32_t po = (uint32_t)((cbase >> 1) + nt * 4 + (lane & 3)) * 4;
            #pragma unroll
            for (int mt = 0; mt < 2; mt++) {
                *(uint32_t*)(smem + bx + (mt * 16 + g) * ROW_B + po) = acc[nt][mt][0];
                *(uint32_t*)(smem + bx + (mt * 16 + g + 8) * ROW_B + po) = acc[nt][mt][1];
            }
        }
        asm volatile("bar.sync %0, 64;" :: "r"(barid) : "memory");   // exch + bh free

        const int s_next = *pop;
        const bool hv = (s_next < NUM_S32);
        const float* xnp = x + ((size_t)s_next * 32 + srow) * 128 + lane * 4;

        float4 v[8];
        if (hv) {
            #pragma unroll
            for (int i = 0; i < 8; i++) v[i] = *(const float4*)(xnp + (size_t)i * 128);
        }

        // ---- epilogue rows srow..srow+7 (covers LDG batch1 latency) ----
        #pragma unroll
        for (int i = 0; i < 8; i++) {
            int r = srow + i;
            uint2 mw = *(const uint2*)(smem + bx + r * ROW_B + lane * 8);
            float4 xv = *(const float4*)(x + (rbase + (size_t)r) * 128 + lane * 4);
            float2 p0 = unpackhf(mw.x), p1 = unpackhf(mw.y);
            float z0 = DT_STEP * (p0.x + bq.x), z1 = DT_STEP * (p1.x + bq.z);
            float w0 = DT_STEP * (p0.y + bq.y), w1 = DT_STEP * (p1.y + bq.w);
            float e0 = fmaf(z0, fmaf(z0, fmaf(z0, 1.f / 6.f, 0.5f), 1.f), 1.f);
            float e1 = fmaf(z1, fmaf(z1, fmaf(z1, 1.f / 6.f, 0.5f), 1.f), 1.f);
            float w0s = w0 * w0, w1s = w1 * w1;
            float sn0 = w0 * fmaf(w0s, -1.f / 6.f, 1.f);
            float sn1 = w1 * fmaf(w1s, -1.f / 6.f, 1.f);
            float cs0 = fmaf(w0s, fmaf(w0s, 1.f / 24.f, -0.5f), 1.f);
            float cs1 = fmaf(w1s, fmaf(w1s, 1.f / 24.f, -0.5f), 1.f);
            float4 o;
            o.x = e0 * (cs0 * xv.x - sn0 * xv.y);
            o.y = e0 * (sn0 * xv.x + cs0 * xv.y);
            o.z = e1 * (cs1 * xv.z - sn1 * xv.w);
            o.w = e1 * (sn1 * xv.z + cs1 * xv.w);
            *(float4*)(out + (rbase + (size_t)r) * 128 + lane * 4) = o;
        }

        // ---- stage batch1 into bh; issue LDG batch2 ----
        if (hv) {
            #pragma unroll
            for (int i = 0; i < 8; i++)
                *(uint2*)(smem + bh + (srow + i) * ROW_B + lane * 8) =
                    make_uint2(packhf(v[i].x, v[i].y), packhf(v[i].z, v[i].w));
            #pragma unroll
            for (int i = 0; i < 8; i++) v[i] = *(const float4*)(xnp + (size_t)(i + 8) * 128);
        }

        // ---- epilogue rows srow+8..srow+15 (covers LDG batch2 latency) ----
        #pragma unroll
        for (int i = 8; i < 16; i++) {
            int r = srow + i;
            uint2 mw = *(const uint2*)(smem + bx + r * ROW_B + lane * 8);
            float4 xv = *(const float4*)(x + (rbase + (size_t)r) * 128 + lane * 4);
            float2 p0 = unpackhf(mw.x), p1 = unpackhf(mw.y);
            float z0 = DT_STEP * (p0.x + bq.x), z1 = DT_STEP * (p1.x + bq.z);
            float w0 = DT_STEP * (p0.y + bq.y), w1 = DT_STEP * (p1.y + bq.w);
            float e0 = fmaf(z0, fmaf(z0, fmaf(z0, 1.f / 6.f, 0.5f), 1.f), 1.f);
            float e1 = fmaf(z1, fmaf(z1, fmaf(z1, 1.f / 6.f, 0.5f), 1.f), 1.f);
            float w0s = w0 * w0, w1s = w1 * w1;
            float sn0 = w0 * fmaf(w0s, -1.f / 6.f, 1.f);
            float sn1 = w1 * fmaf(w1s, -1.f / 6.f, 1.f);
            float cs0 = fmaf(w0s, fmaf(w0s, 1.f / 24.f, -0.5f), 1.f);
            float cs1 = fmaf(w1s, fmaf(w1s, 1.f / 24.f, -0.5f), 1.f);
            float4 o;
            o.x = e0 * (cs0 * xv.x - sn0 * xv.y);
            o.y = e0 * (sn0 * xv.x + cs0 * xv.y);
            o.z = e1 * (cs1 * xv.z - sn1 * xv.w);
            o.w = e1 * (sn1 * xv.z + cs1 * xv.w);
            *(float4*)(out + (rbase + (size_t)r) * 128 + lane * 4) = o;
        }

        // ---- stage batch2 into bh ----
        if (hv) {
            #pragma unroll
            for (int i = 0; i < 8; i++)
                *(uint2*)(smem + bh + (srow + 8 + i) * ROW_B + lane * 8) =
                    make_uint2(packhf(v[i].x, v[i].y), packhf(v[i].z, v[i].w));
        }
        asm volatile("bar.sync %0, 64;" :: "r"(barid) : "memory");   // next-x published

        // swap strip roles: bh now holds x, bx becomes the next H strip
        uint32_t tmp = bx; bx = bh; bh = tmp;
        s = s_next;
    }
}

// ---------------- launch ----------------
extern "C" void kernel_launch(void* const* d_in, const int* in_sizes, int n_in,
                              void* d_out, int out_size) {
    const float* x  = (const float*)d_in[0];
    const float* W1 = (const float*)d_in[1];
    const float* b1 = (const float*)d_in[2];
    const float* W2 = (const float*)d_in[3];
    const float* b2 = (const float*)d_in[4];
    float* out = (float*)d_out;

    cudaFuncSetAttribute(koopman_m32f,
                         cudaFuncAttributeMaxDynamicSharedMemorySize, S_TOT);
    reset_ctr<<<1, 1>>>();
    koopman_m32f<<<GRID_SMS, 512, S_TOT>>>(x, W1, b1, W2, b2, out);
}

// round 15
// speedup vs baseline: 1.2661x; 1.2661x over previous
#include <cuda_runtime.h>
#include <cuda_fp16.h>
#include <cstdint>

#define DT_STEP 0.01f
#define GRID_SMS 152
#define NUM_TILES 1024                  // 131072 rows / 128
#define ROW_B 272                       // 128 f16 (256B) + 16B pad
#define T32 (32 * ROW_B)                // 32-row strip = 8704 B

#define S_W1  0
#define S_W2  (S_W1 + 128 * ROW_B)
#define S_B1  (S_W2 + 128 * ROW_B)
#define S_B2  (S_B1 + 512)
#define S_Q   (S_B2 + 512)              // 4 quads x 2 strips (roles swap)
#define S_TOT (S_Q + 4 * 2 * T32)       // 70656 + 69632 = 140288 B

// ---------------- helpers ----------------
static __device__ __forceinline__ uint32_t smem_u32(const void* p) {
    uint32_t a;
    asm("{ .reg .u64 t; cvta.to.shared.u64 t, %1; cvt.u32.u64 %0, t; }" : "=r"(a) : "l"(p));
    return a;
}

static __device__ __forceinline__ uint32_t packhf(float a, float b) {
    __half2 t = __floats2half2_rn(a, b);
    return *reinterpret_cast<uint32_t*>(&t);
}

static __device__ __forceinline__ float2 unpackhf(uint32_t v) {
    return __half22float2(*reinterpret_cast<__half2*>(&v));
}

static __device__ __forceinline__ float tanh_fast(float v) {
    float r;
    asm("tanh.approx.f32 %0, %1;" : "=f"(r) : "f"(v));
    return r;
}

static __device__ __forceinline__ void ldsm_x4(uint32_t* r, uint32_t addr) {
    asm volatile("ldmatrix.sync.aligned.m8n8.x4.shared.b16 {%0,%1,%2,%3}, [%4];"
                 : "=r"(r[0]), "=r"(r[1]), "=r"(r[2]), "=r"(r[3]) : "r"(addr));
}

static __device__ __forceinline__ void ldsm_x4_t(uint32_t* r, uint32_t addr) {
    asm volatile("ldmatrix.sync.aligned.m8n8.x4.trans.shared.b16 {%0,%1,%2,%3}, [%4];"
                 : "=r"(r[0]), "=r"(r[1]), "=r"(r[2]), "=r"(r[3]) : "r"(addr));
}

static __device__ __forceinline__ void mma16816h(uint32_t* d, const uint32_t* a,
                                                 const uint32_t* b) {
    asm volatile("mma.sync.aligned.m16n8k16.row.col.f16.f16.f16.f16 "
                 "{%0,%1}, {%2,%3,%4,%5}, {%6,%7}, {%0,%1};"
                 : "+r"(d[0]), "+r"(d[1])
                 : "r"(a[0]), "r"(a[1]), "r"(a[2]), "r"(a[3]), "r"(b[0]), "r"(b[1]));
}

// 32x32 warp GEMM: A = 32 rows (all 16 A-frags hoisted up front),
// B = N-quarter of W, depth-1 prefetched. acc[4 nt][2 mt][2].
static __device__ __forceinline__ void gemm32x32(uint32_t abase, uint32_t wl,
                                                 uint32_t acc[4][2][2]) {
    // hoist ALL A-fragments: kt = 0..7 (K=128), mt = 0..1 (rows 0-15 / 16-31)
    uint32_t afr[8][2][4];
    #pragma unroll
    for (int kt = 0; kt < 8; kt++)
        #pragma unroll
        for (int mt = 0; mt < 2; mt++)
            ldsm_x4(afr[kt][mt], abase + (uint32_t)(mt * 16) * ROW_B + (uint32_t)kt * 32);

    // pure B stream: (nt, q) sequence, depth-1 prefetch
    uint32_t bb[2][4];
    ldsm_x4_t(bb[0], wl);               // (nt0, q0)
    int cur = 0;
    #pragma unroll
    for (int nt = 0; nt < 4; nt++) {
        #pragma unroll
        for (int q = 0; q < 4; q++) {
            const int idx = nt * 4 + q;
            if (idx < 15) {
                const int nn = (idx + 1) >> 2, nq = (idx + 1) & 3;
                ldsm_x4_t(bb[cur ^ 1], wl + (uint32_t)nq * (32 * ROW_B)
                                          + (uint32_t)nn * 16);
            }
            #pragma unroll
            for (int mt = 0; mt < 2; mt++)
                #pragma unroll
                for (int kt = 0; kt < 2; kt++)
                    mma16816h(acc[nt][mt], afr[q * 2 + kt][mt], &bb[cur][kt * 2]);
            cur ^= 1;
        }
    }
}

// ---------------- kernel ----------------
__global__ void __launch_bounds__(512, 1)
koopman_quadf(const float* __restrict__ x, const float* __restrict__ W1,
              const float* __restrict__ b1, const float* __restrict__ W2,
              const float* __restrict__ b2, float* __restrict__ out)
{
    extern __shared__ char smem[];
    const uint32_t sb = smem_u32(smem);
    const int tid  = threadIdx.x;
    const int lane = tid & 31;
    const int w    = tid >> 5;          // 0..15
    const int quad = w >> 2;            // 0..3
    const int wp   = w & 3;             // N-quarter owner
    const int g    = lane >> 2;
    const int t2   = (lane & 3) * 2;
    const int barid = quad + 1;

    // ---- one-time: stage W1, W2 (f16, padded rows) + biases ----
    #pragma unroll
    for (int j = 0; j < 8; j++) {
        int idx = j * 512 + tid;
        int r = idx >> 5, c4 = idx & 31;
        float4 wv = *(const float4*)(W1 + (size_t)r * 128 + c4 * 4);
        *(uint2*)(smem + S_W1 + r * ROW_B + c4 * 8) =
            make_uint2(packhf(wv.x, wv.y), packhf(wv.z, wv.w));
        float4 wv2 = *(const float4*)(W2 + (size_t)r * 128 + c4 * 4);
        *(uint2*)(smem + S_W2 + r * ROW_B + c4 * 8) =
            make_uint2(packhf(wv2.x, wv2.y), packhf(wv2.z, wv2.w));
    }
    if (tid < 128) {
        ((float*)(smem + S_B1))[tid] = b1[tid];
        ((float*)(smem + S_B2))[tid] = b2[tid];
    }
    __syncthreads();                    // only CTA-wide sync

    const uint32_t wl1 = sb + S_W1 + (uint32_t)lane * ROW_B + (uint32_t)wp * 64;
    const uint32_t wl2 = sb + S_W2 + (uint32_t)lane * ROW_B + (uint32_t)wp * 64;
    const int cbase = wp * 32;
    const float* fb1 = (const float*)(smem + S_B1) + cbase + t2;
    const float4 bq = *(const float4*)((const float*)(smem + S_B2) + lane * 4);

    const uint32_t amRow = (uint32_t)((lane & 7) + ((lane >> 3) & 1) * 8) * ROW_B
                         + (uint32_t)(lane >> 4) * 16;
    const int srow = wp * 8;            // this warp stages/epilogues 8 rows

    uint32_t bx = (uint32_t)(S_Q + quad * 2 * T32);   // x strip (role swaps)
    uint32_t bh = bx + T32;                            // H strip (role swaps)

    // ---- prologue: stage first tile's band ----
    {
        const float* xr = x + ((size_t)blockIdx.x * 128 + quad * 32 + srow) * 128 + lane * 4;
        #pragma unroll
        for (int i = 0; i < 8; i++) {
            float4 v = *(const float4*)(xr + (size_t)i * 128);
            *(uint2*)(smem + bx + (srow + i) * ROW_B + lane * 8) =
                make_uint2(packhf(v.x, v.y), packhf(v.z, v.w));
        }
    }
    asm volatile("bar.sync %0, 128;" :: "r"(barid) : "memory");

    for (int t = blockIdx.x; t < NUM_TILES; t += GRID_SMS) {
        const size_t rbase = (size_t)t * 128 + quad * 32;

        // ---- GEMM1: acc = X(32 rows) @ W1(:, quarter) ----
        uint32_t acc[4][2][2];
        #pragma unroll
        for (int nt = 0; nt < 4; nt++)
            #pragma unroll
            for (int mt = 0; mt < 2; mt++)
                { acc[nt][mt][0] = 0u; acc[nt][mt][1] = 0u; }
        gemm32x32(sb + bx + amRow, wl1, acc);

        // ---- epilogue 1: H quarter = tanh(acc + b1) -> bh ----
        #pragma unroll
        for (int nt = 0; nt < 4; nt++) {
            float2 bv = *(const float2*)(fb1 + nt * 8);
            int c = cbase + nt * 8 + t2;
            #pragma unroll
            for (int mt = 0; mt < 2; mt++) {
                float2 p = unpackhf(acc[nt][mt][0]);
                float2 q = unpackhf(acc[nt][mt][1]);
                *(uint32_t*)(smem + bh + (mt * 16 + g) * ROW_B + c * 2) =
                    packhf(tanh_fast(p.x + bv.x), tanh_fast(p.y + bv.y));
                *(uint32_t*)(smem + bh + (mt * 16 + g + 8) * ROW_B + c * 2) =
                    packhf(tanh_fast(q.x + bv.x), tanh_fast(q.y + bv.y));
            }
        }
        asm volatile("bar.sync %0, 128;" :: "r"(barid) : "memory");   // H ready

        // ---- GEMM2: acc = H(32 rows) @ W2(:, quarter) ----
        #pragma unroll
        for (int nt = 0; nt < 4; nt++)
            #pragma unroll
            for (int mt = 0; mt < 2; mt++)
                { acc[nt][mt][0] = 0u; acc[nt][mt][1] = 0u; }
        gemm32x32(sb + bh + amRow, wl2, acc);

        // ---- exchange: raw f16 (mu,omega) pairs -> bx (x dead after GEMM1) ----
        #pragma unroll
        for (int nt = 0; nt < 4; nt++) {
            uint32_t po = (uint32_t)((cbase >> 1) + nt * 4 + (lane & 3)) * 4;
            #pragma unroll
            for (int mt = 0; mt < 2; mt++) {
                *(uint32_t*)(smem + bx + (mt * 16 + g) * ROW_B + po) = acc[nt][mt][0];
                *(uint32_t*)(smem + bx + (mt * 16 + g + 8) * ROW_B + po) = acc[nt][mt][1];
            }
        }
        asm volatile("bar.sync %0, 128;" :: "r"(barid) : "memory");   // exch + bh free

        const int tn = t + GRID_SMS;
        const bool hn = (tn < NUM_TILES);
        const float* xnp = x + (((size_t)tn * 128) + quad * 32 + srow) * 128 + lane * 4;

        // LDG next band (latency hidden under the epilogue below)
        float4 v[8];
        if (hn) {
            #pragma unroll
            for (int i = 0; i < 8; i++) v[i] = *(const float4*)(xnp + (size_t)i * 128);
        }

        // ---- epilogue 2 (coalesced): rows srow..srow+7, full 128 cols ----
        #pragma unroll
        for (int i = 0; i < 8; i++) {
            int r = srow + i;
            uint2 mw = *(const uint2*)(smem + bx + r * ROW_B + lane * 8);
            float4 xv = *(const float4*)(x + (rbase + (size_t)r) * 128 + lane * 4);
            float2 p0 = unpackhf(mw.x), p1 = unpackhf(mw.y);
            float z0 = DT_STEP * (p0.x + bq.x), z1 = DT_STEP * (p1.x + bq.z);
            float w0 = DT_STEP * (p0.y + bq.y), w1 = DT_STEP * (p1.y + bq.w);
            float e0 = fmaf(z0, fmaf(z0, fmaf(z0, 1.f / 6.f, 0.5f), 1.f), 1.f);
            float e1 = fmaf(z1, fmaf(z1, fmaf(z1, 1.f / 6.f, 0.5f), 1.f), 1.f);
            float w0s = w0 * w0, w1s = w1 * w1;
            float sn0 = w0 * fmaf(w0s, -1.f / 6.f, 1.f);
            float sn1 = w1 * fmaf(w1s, -1.f / 6.f, 1.f);
            float cs0 = fmaf(w0s, fmaf(w0s, 1.f / 24.f, -0.5f), 1.f);
            float cs1 = fmaf(w1s, fmaf(w1s, 1.f / 24.f, -0.5f), 1.f);
            float4 o;
            o.x = e0 * (cs0 * xv.x - sn0 * xv.y);
            o.y = e0 * (sn0 * xv.x + cs0 * xv.y);
            o.z = e1 * (cs1 * xv.z - sn1 * xv.w);
            o.w = e1 * (sn1 * xv.z + cs1 * xv.w);
            *(float4*)(out + (rbase + (size_t)r) * 128 + lane * 4) = o;
        }

        // ---- stage next band into bh ----
        if (hn) {
            #pragma unroll
            for (int i = 0; i < 8; i++)
                *(uint2*)(smem + bh + (srow + i) * ROW_B + lane * 8) =
                    make_uint2(packhf(v[i].x, v[i].y), packhf(v[i].z, v[i].w));
        }
        asm volatile("bar.sync %0, 128;" :: "r"(barid) : "memory");   // next-x published

        // swap strip roles: bh now holds x, bx becomes next H strip
        uint32_t tmp = bx; bx = bh; bh = tmp;
    }
}

// ---------------- launch ----------------
extern "C" void kernel_launch(void* const* d_in, const int* in_sizes, int n_in,
                              void* d_out, int out_size) {
    const float* x  = (const float*)d_in[0];
    const float* W1 = (const float*)d_in[1];
    const float* b1 = (const float*)d_in[2];
    const float* W2 = (const float*)d_in[3];
    const float* b2 = (const float*)d_in[4];
    float* out = (float*)d_out;

    cudaFuncSetAttribute(koopman_quadf,
                         cudaFuncAttributeMaxDynamicSharedMemorySize, S_TOT);
    koopman_quadf<<<GRID_SMS, 512, S_TOT>>>(x, W1, b1, W2, b2, out);
}